// round 17
// baseline (speedup 1.0000x reference)
#include <cuda_runtime.h>
#include <math_constants.h>

// Morphological opening (10x10 min then 10x10 max, SAME pad lo=4/hi=5),
// NHWC [16,512,512,8] f32. Persistent y-strip kernel: each block owns a
// 64-row x 32-col x 8ch segment and loops 4 chunks of 16 output rows,
// keeping vertical-min (B) and dilated-x (F) rows in 28-row smem RINGS so
// the 9-row vertical halo is computed once per segment instead of per tile.
// Stages per chunk: V1 gmem->B (streaming v-min, 16 new rows steady-state),
// Hfused B->F (h-min+h-max chained in registers), V2 F->gmem (v-max).

#define H_  512
#define W_  512
#define NT  256

#define RING 28
#define BW   201          // f2 per B ring row (200 used + 1 pad)
#define FW   129          // f2 per F ring row (128 used + 1 pad)
#define F_OFF (RING * BW)               // 5628
#define SMEM_F2 (F_OFF + RING * FW)     // 9240
#define SMEM_BYTES (SMEM_F2 * 8)        // 73,920 -> 3 blocks/SM

__device__ __forceinline__ float2 mn2(float2 a, float2 b) {
    return make_float2(fminf(a.x,b.x), fminf(a.y,b.y));
}
__device__ __forceinline__ float2 mx2(float2 a, float2 b) {
    return make_float2(fmaxf(a.x,b.x), fmaxf(a.y,b.y));
}
template<bool MN>
__device__ __forceinline__ float2 op2(float2 a, float2 b) { return MN ? mn2(a,b) : mx2(a,b); }

// Streaming van Herk: out[i] = OP(in[i..i+9]) for i in [0,NOUT).
template<bool MN, int NOUT, class L, class S>
__device__ __forceinline__ void svh(L ld, S st) {
    constexpr int NIN  = NOUT + 9;
    constexpr int NBLK = (NOUT + 8) / 9;
    float2 s[9];
    #pragma unroll
    for (int t = 0; t < 9; t++) s[t] = ld(t);
    #pragma unroll
    for (int j = 7; j >= 0; j--) s[j] = op2<MN>(s[j], s[j+1]);
    #pragma unroll
    for (int m = 0; m < NBLK; m++) {
        const int base = 9 * m;
        const int ycnt = (NIN - 9*(m+1) < 9) ? (NIN - 9*(m+1)) : 9;
        float2 y[9];
        #pragma unroll
        for (int t = 0; t < 9; t++) if (t < ycnt) y[t] = ld(9*(m+1) + t);
        float2 pr = y[0];
        st(base, op2<MN>(s[0], pr));
        #pragma unroll
        for (int r = 1; r < 9; r++) {
            if (base + r < NOUT) {
                pr = op2<MN>(pr, y[r]);
                st(base + r, op2<MN>(s[r], pr));
            }
        }
        if (m + 1 < NBLK) {
            #pragma unroll
            for (int j = 7; j >= 0; j--) y[j] = op2<MN>(y[j], y[j+1]);
            #pragma unroll
            for (int t = 0; t < 9; t++) s[t] = y[t];
        }
    }
}

__global__ __launch_bounds__(NT, 3)
void opening_kernel(const float2* __restrict__ in2, float2* __restrict__ out2) {
    extern __shared__ float2 sm[];
    float2* Bs = sm;            // B[p][cQ], p = ring row, cQ = cb*4+q
    float2* Fs = sm + F_OFF;    // F[p][cQ'']

    const int b   = blockIdx.z;
    const int gw0 = blockIdx.x * 32;
    const int Y0  = blockIdx.y * 64;
    const int tid = threadIdx.x;

    const size_t chanBase = (size_t)b * ((size_t)H_ * W_ * 4);  // f2 units
    const float2 INF2  = make_float2( CUDART_INF_F,  CUDART_INF_F);
    const float2 NINF2 = make_float2(-CUDART_INF_F, -CUDART_INF_F);

    // phys ring row of eroded-row yE = Y0-4
    int pbase = (Y0 - 4) % RING; if (pbase < 0) pbase += RING;

    for (int c = 0; c < 4; c++) {
        const int gy   = Y0 + 16 * c;
        const int cnt  = (c == 0) ? 25 : 16;            // new B/F rows this chunk
        const int yEw0 = (c == 0) ? (Y0 - 4) : (gy + 5); // first new eroded row
        const int pw0  = (c == 0) ? pbase : (pbase + 16 * c + 9) % RING;

        // ---- V1: vertical min, gmem -> B ring (coalesced). 200 tasks. ----
        if (tid < 200) {
            int cQ = tid, cb = cQ >> 2, q = cQ & 3;
            int gx = gw0 + cb - 8;
            if ((unsigned)gx >= W_) {
                for (int i = 0; i < cnt; i++) {
                    int p = pw0 + i; if (p >= RING) p -= RING;
                    Bs[p * BW + cQ] = INF2;
                }
            } else {
                const float2* src = in2 + chanBase + (size_t)gx * 4 + q;
                int inLo = yEw0 - 4;
                auto st = [&](int i, float2 v) {
                    int p = pw0 + i; if (p >= RING) p -= RING;
                    Bs[p * BW + cQ] = v;
                };
                bool inter = (inLo >= 0) && (inLo + cnt + 8 < H_);
                if (inter) {
                    auto ld = [&](int t) { return src[(size_t)(inLo + t) * (W_ * 4)]; };
                    if (c == 0) svh<true, 25>(ld, st); else svh<true, 16>(ld, st);
                } else {
                    auto ld = [&](int t) {
                        int gyy = inLo + t; float2 v = INF2;
                        if ((unsigned)gyy < H_) v = src[(size_t)gyy * (W_ * 4)];
                        return v;
                    };
                    if (c == 0) svh<true, 25>(ld, st); else svh<true, 16>(ld, st);
                }
            }
        }
        __syncthreads();

        // ---- Hfused: B -> F (h-min + h-max chained in regs). 8*cnt tasks. ----
        if (tid < 8 * cnt) {
            int e    = tid % cnt;
            int t2   = tid / cnt;      // 0..7
            int q    = t2 & 3;
            int half = t2 >> 2;
            int cB0  = half * 16;
            int yE   = yEw0 + e;
            int p    = pw0 + e; if (p >= RING) p -= RING;
            const float2* pB = Bs + p * BW + (cB0 * 4 + q);   // x-step 4 f2
            float2*       pF = Fs + p * FW + (cB0 * 4 + q);
            bool rowOK    = ((unsigned)yE < H_);
            int  colBase  = gw0 + cB0 - 4;
            bool needMask = !(rowOK && colBase >= 0 && colBase + 24 < W_);

            float2 sB[9], yB[9], sE[9], eb[9];
            #pragma unroll
            for (int t = 0; t < 9; t++) sB[t] = pB[t * 4];
            #pragma unroll
            for (int j = 7; j >= 0; j--) sB[j] = mn2(sB[j], sB[j+1]);

            // --- produce E[0..8] ---
            #pragma unroll
            for (int t = 0; t < 9; t++) yB[t] = pB[(9 + t) * 4];
            {
                float2 pr = yB[0];
                eb[0] = mn2(sB[0], pr);
                #pragma unroll
                for (int r = 1; r < 9; r++) { pr = mn2(pr, yB[r]); eb[r] = mn2(sB[r], pr); }
            }
            if (needMask) {
                #pragma unroll
                for (int r = 0; r < 9; r++)
                    if (!rowOK || (unsigned)(colBase + r) >= W_) eb[r] = NINF2;
            }
            #pragma unroll
            for (int t = 0; t < 9; t++) sE[t] = eb[t];
            #pragma unroll
            for (int j = 7; j >= 0; j--) sE[j] = mx2(sE[j], sE[j+1]);
            #pragma unroll
            for (int j = 7; j >= 0; j--) yB[j] = mn2(yB[j], yB[j+1]);
            #pragma unroll
            for (int t = 0; t < 9; t++) sB[t] = yB[t];

            // --- produce E[9..17], emit F[0..8] ---
            #pragma unroll
            for (int t = 0; t < 9; t++) yB[t] = pB[(18 + t) * 4];
            {
                float2 pr = yB[0];
                eb[0] = mn2(sB[0], pr);
                #pragma unroll
                for (int r = 1; r < 9; r++) { pr = mn2(pr, yB[r]); eb[r] = mn2(sB[r], pr); }
            }
            if (needMask) {
                #pragma unroll
                for (int r = 0; r < 9; r++)
                    if (!rowOK || (unsigned)(colBase + 9 + r) >= W_) eb[r] = NINF2;
            }
            {
                float2 pr = eb[0];
                pF[0] = mx2(sE[0], pr);
                #pragma unroll
                for (int r = 1; r < 9; r++) { pr = mx2(pr, eb[r]); pF[r * 4] = mx2(sE[r], pr); }
            }
            #pragma unroll
            for (int j = 7; j >= 0; j--) eb[j] = mx2(eb[j], eb[j+1]);
            #pragma unroll
            for (int t = 0; t < 9; t++) sE[t] = eb[t];
            #pragma unroll
            for (int j = 7; j >= 0; j--) yB[j] = mn2(yB[j], yB[j+1]);
            #pragma unroll
            for (int t = 0; t < 9; t++) sB[t] = yB[t];

            // --- produce E[18..24] (7), emit F[9..15] (7) ---
            #pragma unroll
            for (int t = 0; t < 7; t++) yB[t] = pB[(27 + t) * 4];
            {
                float2 pr = yB[0];
                eb[0] = mn2(sB[0], pr);
                #pragma unroll
                for (int r = 1; r < 7; r++) { pr = mn2(pr, yB[r]); eb[r] = mn2(sB[r], pr); }
            }
            if (needMask) {
                #pragma unroll
                for (int r = 0; r < 7; r++)
                    if (!rowOK || (unsigned)(colBase + 18 + r) >= W_) eb[r] = NINF2;
            }
            {
                float2 pr = eb[0];
                pF[9 * 4] = mx2(sE[0], pr);
                #pragma unroll
                for (int r = 1; r < 7; r++) { pr = mx2(pr, eb[r]); pF[(9 + r) * 4] = mx2(sE[r], pr); }
            }
        }
        __syncthreads();

        // ---- V2: vertical max F -> gmem (coalesced). 128 tasks. ----
        if (tid < 128) {
            int cQ  = tid;
            int pv0 = (pbase + 16 * c) % RING;
            float2* qo = out2 + chanBase + ((size_t)gy * W_ + gw0) * 4 + cQ;
            auto ld = [&](int t) {
                int p = pv0 + t; if (p >= RING) p -= RING;
                return Fs[p * FW + cQ];
            };
            auto st = [&](int i, float2 v) { qo[(size_t)i * (W_ * 4)] = v; };
            svh<false, 16>(ld, st);
        }
        // no barrier needed here: next V1 writes B only; F reuse is fenced by
        // the two barriers above before Hfused touches F again.
    }
}

extern "C" void kernel_launch(void* const* d_in, const int* in_sizes, int n_in,
                              void* d_out, int out_size) {
    const float2* in  = (const float2*)d_in[0];
    float2* out = (float2*)d_out;

    cudaFuncSetAttribute(opening_kernel,
                         cudaFuncAttributeMaxDynamicSharedMemorySize, SMEM_BYTES);

    dim3 grid(W_ / 32, H_ / 64, 16);
    opening_kernel<<<grid, NT, SMEM_BYTES>>>(in, out);
}